// round 14
// baseline (speedup 1.0000x reference)
#include <cuda_runtime.h>

// out: [16384, 2046] f32 = tanh(row) broadcast over batch rows; row depends
// only on kernel_weights[6]. `values` is shape-only (never read).
//
// FINAL — converged at the hardware floor (session record 25.056us).
//
// Convergence evidence (R4..R13, 10 structurally distinct variants):
//   kernel-internal time 21.15-22.2us, TOTAL pinned 25.05-25.3us.
//   Invariant across: store width (32/128/256b), cache policy (wb/wt/cs),
//   L2-residency splits, tiling period (2/4/16 rows), wave shape
//   (1184 persistent vs 2048 waved CTAs), prologue cost (libm vs approx),
//   STG vs TMA bulk. Work conservation: the replay period = 134MB mandatory
//   output at ~5.3TB/s sustained DRAM write + fixed replay launch overhead.
//   Bytes are fixed by the problem; skip-write caching is prohibited.
//
// Structure: pattern period = 2 rows = 4092 floats = 1023 float4 (16B
// aligned; 4092 = 2*2046). Each thread owns one float4 column slot, computes
// its 4 values once into registers, then streams write-through STG.128 down
// the batch dimension (wt: single LTS pass, no write-allocate/writeback —
// the R4 measured win over evict-first). libm tanhf/expf kept for maximum
// accuracy margin (rel_err 2.1e-7 vs 1e-3 gate).

#define BS       16384
#define L_OUT    2046
#define GROUPS   (BS / 2)              // 8192 two-row groups
#define F4_PER_G 1023                  // float4 per group
#define TPB      256
#define COL_BLK  4                     // 4*256 = 1024 threads cover 1023 slots
#define G_CHUNKS 512                   // batch split over blockIdx.y
#define G_PER_B  (GROUPS / G_CHUNKS)   // 16 stores per thread

#define NEG_LOG_NORM 1.3836465597893728f   // -log(0.1*sqrt(2*pi))
#define INV_STD      10.0f

__device__ __forceinline__ float row_value(int c, const float* __restrict__ w) {
    const float means[6] = {0.0f, 0.2f, 0.4f, 0.6f, 0.8f, 1.0f};
    float pos = (float)c / (float)L_OUT;
    float acc = 0.0f;
#pragma unroll
    for (int k = 0; k < 6; k++) {
        float z = (pos - means[k]) * INV_STD;
        float pdf = expf(fmaf(-0.5f * z, z, NEG_LOG_NORM));
        acc = fmaf(w[k], pdf, acc);
    }
    return tanhf(acc);
}

__global__ void __launch_bounds__(TPB) bcast_wt_kernel(const float* __restrict__ kw,
                                                       float4* __restrict__ out) {
    int t = blockIdx.x * TPB + threadIdx.x;    // float4 slot within a group
    if (t >= F4_PER_G) return;

    float w[6];
#pragma unroll
    for (int k = 0; k < 6; k++) w[k] = 0.25f * tanhf(__ldg(&kw[k]));

    int e = 4 * t;
    int c0 = e;     if (c0 >= L_OUT) c0 -= L_OUT;
    int c1 = e + 1; if (c1 >= L_OUT) c1 -= L_OUT;
    int c2 = e + 2; if (c2 >= L_OUT) c2 -= L_OUT;
    int c3 = e + 3; if (c3 >= L_OUT) c3 -= L_OUT;

    float4 v;
    v.x = row_value(c0, w);
    v.y = row_value(c1, w);
    v.z = row_value(c2, w);
    v.w = row_value(c3, w);

    float4* p = out + (size_t)blockIdx.y * G_PER_B * F4_PER_G + t;
#pragma unroll 8
    for (int g = 0; g < G_PER_B; g++) {
        __stwt(p, v);          // write-through: one LTS pass, no writeback
        p += F4_PER_G;
    }
}

extern "C" void kernel_launch(void* const* d_in, const int* in_sizes, int n_in,
                              void* d_out, int out_size) {
    const float* kw = (const float*)d_in[1];   // kernel_weights [6]
    dim3 grid(COL_BLK, G_CHUNKS);              // 2048 blocks x 256 threads
    bcast_wt_kernel<<<grid, TPB>>>(kw, (float4*)d_out);
}